// round 2
// baseline (speedup 1.0000x reference)
#include <cuda_runtime.h>
#include <cstddef>

#define NMAX 100000
#define EMAX 1600000

// Scratch (__device__ globals; allocation-free rule)
__device__ float g_f1[NMAX * 64];    // features @ W1
__device__ float g_agg1[NMAX * 64];  // CSR gather of f1
__device__ float g_f2[NMAX * 32];    // relu(agg1 + b1) @ W2
__device__ int   g_cnt[NMAX];        // in-degree histogram
__device__ int   g_rs[NMAX + 1];     // CSR row starts
__device__ int   g_cur[NMAX];        // placement cursors
__device__ int   g_esrc[EMAX];       // CSR src lists grouped by dst

// ---------------------------------------------------------------------------
// CSR build
// ---------------------------------------------------------------------------
__global__ void zero_cnt_kernel(int n) {
    int i = blockIdx.x * blockDim.x + threadIdx.x;
    if (i < n) g_cnt[i] = 0;
}

__global__ void hist_kernel(const int* __restrict__ dst, int n_edges) {
    int i = blockIdx.x * blockDim.x + threadIdx.x;
    if (i < n_edges) atomicAdd(&g_cnt[dst[i]], 1);  // no return use -> RED
}

// Single-block exclusive scan of g_cnt -> g_rs (and copy to g_cur).
__global__ __launch_bounds__(1024) void scan_kernel(int n) {
    __shared__ int sums[1024];
    int t = threadIdx.x;
    int C = (n + 1023) >> 10;
    int lo = t * C;
    int hi = lo + C; if (hi > n) hi = n;
    int s = 0;
    for (int i = lo; i < hi; i++) s += g_cnt[i];
    sums[t] = s;
    __syncthreads();
    // Hillis-Steele inclusive scan
    for (int off = 1; off < 1024; off <<= 1) {
        int v = (t >= off) ? sums[t - off] : 0;
        __syncthreads();
        sums[t] += v;
        __syncthreads();
    }
    int run = sums[t] - s;  // exclusive base
    for (int i = lo; i < hi; i++) {
        g_rs[i] = run;
        g_cur[i] = run;
        run += g_cnt[i];
    }
    if (t == 1023) g_rs[n] = run;
}

__global__ void place_kernel(const int* __restrict__ src,
                             const int* __restrict__ dst, int n_edges) {
    int i = blockIdx.x * blockDim.x + threadIdx.x;
    if (i < n_edges) {
        int p = atomicAdd(&g_cur[dst[i]], 1);
        g_esrc[p] = src[i];
    }
}

// ---------------------------------------------------------------------------
// Tiled GEMM: Y[row] = act(X[row]) @ W, K=64 fixed, N in {64,32}.
// Block = 128 threads, 128-row tile; thread = 8 rows x (N/8) cols.
// A staged in smem XOR-swizzled (phys col = k ^ (row&31)) -> conflict-free
// column reads. Inner product uses packed fma.rn.f32x2 (2 cols per op).
// ---------------------------------------------------------------------------
#define FMA2(acc_, a_, b_) \
    asm("fma.rn.f32x2 %0, %1, %2, %0;" : "+l"(acc_) : "l"(a_), "l"(b_))

template <int N, bool ACT>
__global__ __launch_bounds__(128) void transform_kernel(
    const float* __restrict__ X, const float* __restrict__ W,
    const float* __restrict__ bin, float* __restrict__ Y, int n) {
    __shared__ float As[128 * 64];
    __shared__ float Ws[64 * N + (ACT ? 64 : 0)];
    float* bs = Ws + 64 * N;  // only valid if ACT

    int tid = threadIdx.x;
    for (int i = tid; i < 64 * N; i += 128) Ws[i] = W[i];
    if (ACT && tid < 64) bs[tid] = bin[tid];
    __syncthreads();

    int blk = blockIdx.x * 128;
    // Stage A tile (act applied), XOR swizzle on column index
#pragma unroll
    for (int i = 0; i < 16; i++) {
        int idx = i * 128 + tid;
        int row = idx >> 4, c = idx & 15;
        int gr = blk + row;
        float4 v = make_float4(0.f, 0.f, 0.f, 0.f);
        if (gr < n) v = *(const float4*)(X + (size_t)gr * 64 + c * 4);
        float vv[4] = {v.x, v.y, v.z, v.w};
        int rm = row & 31;
#pragma unroll
        for (int j = 0; j < 4; j++) {
            float x = vv[j];
            if (ACT) x = fmaxf(x + bs[c * 4 + j], 0.f);
            As[row * 64 + ((c * 4 + j) ^ rm)] = x;
        }
    }
    __syncthreads();

    const int CT = N / 8;   // cols per thread
    const int CP = CT / 2;  // col pairs (f32x2)
    int tr = tid >> 3, tc = tid & 7;

    unsigned long long acc[8][CP];
#pragma unroll
    for (int r = 0; r < 8; r++)
#pragma unroll
        for (int p = 0; p < CP; p++) acc[r][p] = 0ULL;

    int rowoff[8], rmask[8];
#pragma unroll
    for (int r = 0; r < 8; r++) {
        int row = tr * 8 + r;
        rowoff[r] = row * 64;
        rmask[r] = row & 31;
    }

#pragma unroll 4
    for (int k = 0; k < 64; k++) {
        unsigned long long b[CP];
#pragma unroll
        for (int p = 0; p < CP; p++)
            b[p] = *(const unsigned long long*)(Ws + k * N + tc * CT + 2 * p);
#pragma unroll
        for (int r = 0; r < 8; r++) {
            float a = As[rowoff[r] + (k ^ rmask[r])];
            unsigned int au = __float_as_uint(a);
            unsigned long long a2;
            asm("mov.b64 %0, {%1, %1};" : "=l"(a2) : "r"(au));
#pragma unroll
            for (int p = 0; p < CP; p++) FMA2(acc[r][p], a2, b[p]);
        }
    }

#pragma unroll
    for (int r = 0; r < 8; r++) {
        int gr = blk + tr * 8 + r;
        if (gr >= n) continue;
        float* yr = Y + (size_t)gr * N + tc * CT;
#pragma unroll
        for (int p = 0; p < CP; p += 2) {
            unsigned int l0, h0, l1, h1;
            asm("mov.b64 {%0, %1}, %2;" : "=r"(l0), "=r"(h0) : "l"(acc[r][p]));
            asm("mov.b64 {%0, %1}, %2;" : "=r"(l1), "=r"(h1) : "l"(acc[r][p + 1]));
            float4 o = make_float4(__uint_as_float(l0), __uint_as_float(h0),
                                   __uint_as_float(l1), __uint_as_float(h1));
            *(float4*)(yr + 2 * p) = o;
        }
    }
}

// ---------------------------------------------------------------------------
// CSR gather-sum, 64-wide rows: half-warp (16 lanes x float4) per node.
// ---------------------------------------------------------------------------
__global__ void gather64_kernel(const float* __restrict__ F,
                                float* __restrict__ O, int n) {
    int g = blockIdx.x * blockDim.x + threadIdx.x;
    int node = g >> 4, lane = g & 15;
    if (node >= n) return;
    int s = g_rs[node], e = g_rs[node + 1];
    float4 acc = make_float4(0.f, 0.f, 0.f, 0.f);
    int i = s;
    for (; i + 4 <= e; i += 4) {
        int s0 = g_esrc[i], s1 = g_esrc[i + 1];
        int s2 = g_esrc[i + 2], s3 = g_esrc[i + 3];
        float4 v0 = *(const float4*)(F + (size_t)s0 * 64 + lane * 4);
        float4 v1 = *(const float4*)(F + (size_t)s1 * 64 + lane * 4);
        float4 v2 = *(const float4*)(F + (size_t)s2 * 64 + lane * 4);
        float4 v3 = *(const float4*)(F + (size_t)s3 * 64 + lane * 4);
        acc.x += (v0.x + v1.x) + (v2.x + v3.x);
        acc.y += (v0.y + v1.y) + (v2.y + v3.y);
        acc.z += (v0.z + v1.z) + (v2.z + v3.z);
        acc.w += (v0.w + v1.w) + (v2.w + v3.w);
    }
    for (; i < e; i++) {
        int si = g_esrc[i];
        float4 v = *(const float4*)(F + (size_t)si * 64 + lane * 4);
        acc.x += v.x; acc.y += v.y; acc.z += v.z; acc.w += v.w;
    }
    *(float4*)(O + (size_t)node * 64 + lane * 4) = acc;
}

// ---------------------------------------------------------------------------
// CSR gather-sum, 32-wide rows, acc initialized with bias b2 (fused init).
// 8 lanes x float4 per node.
// ---------------------------------------------------------------------------
__global__ void gather32_kernel(const float* __restrict__ F,
                                const float* __restrict__ b2,
                                float* __restrict__ O, int n) {
    int g = blockIdx.x * blockDim.x + threadIdx.x;
    int node = g >> 3, lane = g & 7;
    if (node >= n) return;
    int s = g_rs[node], e = g_rs[node + 1];
    float4 acc = *(const float4*)(b2 + lane * 4);
    int i = s;
    for (; i + 4 <= e; i += 4) {
        int s0 = g_esrc[i], s1 = g_esrc[i + 1];
        int s2 = g_esrc[i + 2], s3 = g_esrc[i + 3];
        float4 v0 = *(const float4*)(F + (size_t)s0 * 32 + lane * 4);
        float4 v1 = *(const float4*)(F + (size_t)s1 * 32 + lane * 4);
        float4 v2 = *(const float4*)(F + (size_t)s2 * 32 + lane * 4);
        float4 v3 = *(const float4*)(F + (size_t)s3 * 32 + lane * 4);
        acc.x += (v0.x + v1.x) + (v2.x + v3.x);
        acc.y += (v0.y + v1.y) + (v2.y + v3.y);
        acc.z += (v0.z + v1.z) + (v2.z + v3.z);
        acc.w += (v0.w + v1.w) + (v2.w + v3.w);
    }
    for (; i < e; i++) {
        int si = g_esrc[i];
        float4 v = *(const float4*)(F + (size_t)si * 32 + lane * 4);
        acc.x += v.x; acc.y += v.y; acc.z += v.z; acc.w += v.w;
    }
    *(float4*)(O + (size_t)node * 32 + lane * 4) = acc;
}

// ---------------------------------------------------------------------------
// kernel_launch
// inputs: features[f32 N*64], src[i32 E], dst[i32 E], W1[f32 64*64],
//         b1[f32 64], W2[f32 64*32], b2[f32 32]; out: f32 N*32
// ---------------------------------------------------------------------------
extern "C" void kernel_launch(void* const* d_in, const int* in_sizes, int n_in,
                              void* d_out, int out_size) {
    const float* features = (const float*)d_in[0];
    const int*   src      = (const int*)d_in[1];
    const int*   dst      = (const int*)d_in[2];
    const float* W1       = (const float*)d_in[3];
    const float* b1       = (const float*)d_in[4];
    const float* W2       = (const float*)d_in[5];
    const float* b2       = (const float*)d_in[6];
    float*       out      = (float*)d_out;

    int n_nodes = in_sizes[0] / 64;
    int n_edges = in_sizes[1];

    void *pf1, *pagg1, *pf2;
    cudaGetSymbolAddress(&pf1, g_f1);
    cudaGetSymbolAddress(&pagg1, g_agg1);
    cudaGetSymbolAddress(&pf2, g_f2);
    float* f1   = (float*)pf1;
    float* agg1 = (float*)pagg1;
    float* f2   = (float*)pf2;

    int eb = (n_edges + 255) / 256;
    int tb = (n_nodes + 127) / 128;

    // CSR build
    zero_cnt_kernel<<<(n_nodes + 255) / 256, 256>>>(n_nodes);
    hist_kernel<<<eb, 256>>>(dst, n_edges);
    scan_kernel<<<1, 1024>>>(n_nodes);
    place_kernel<<<eb, 256>>>(src, dst, n_edges);

    // Layer 1: f1 = X @ W1 ; agg1 = segment_sum(f1[src] -> dst)
    transform_kernel<64, false><<<tb, 128>>>(features, W1, nullptr, f1, n_nodes);
    gather64_kernel<<<(n_nodes * 16 + 255) / 256, 256>>>(f1, agg1, n_nodes);

    // Layer 2: f2 = relu(agg1 + b1) @ W2 ; out = b2 + segment_sum(f2[src] -> dst)
    transform_kernel<32, true><<<tb, 128>>>(agg1, W2, b1, f2, n_nodes);
    gather32_kernel<<<(n_nodes * 8 + 255) / 256, 256>>>(f2, b2, out, n_nodes);
}

// round 3
// speedup vs baseline: 2.0410x; 2.0410x over previous
#include <cuda_runtime.h>
#include <cstddef>

#define NMAX 100000
#define EMAX 1600000
#define NCHUNK_MAX ((NMAX + 1023) / 1024 + 1)

// Scratch (__device__ globals; allocation-free rule)
__device__ float g_f1[NMAX * 64];    // features @ W1
__device__ float g_agg1[NMAX * 64];  // CSR gather of f1
__device__ float g_f2[NMAX * 32];    // relu(agg1 + b1) @ W2
__device__ int   g_cnt[NMAX];        // in-degree histogram
__device__ int   g_rs[NMAX + 4];     // CSR row starts
__device__ int   g_cur[NMAX + 4];    // placement cursors
__device__ int   g_esrc[EMAX];       // CSR src lists grouped by dst
__device__ int   g_bsum[NCHUNK_MAX]; // per-1024-chunk sums
__device__ int   g_bbase[NCHUNK_MAX];// per-chunk exclusive bases

// ---------------------------------------------------------------------------
// CSR build
// ---------------------------------------------------------------------------
__global__ void zero_cnt_kernel(int n4) {
    int i = blockIdx.x * blockDim.x + threadIdx.x;
    if (i < n4) ((int4*)g_cnt)[i] = make_int4(0, 0, 0, 0);
}

__global__ void hist_kernel(const int* __restrict__ dst, int n_edges) {
    int i = blockIdx.x * blockDim.x + threadIdx.x;
    if (i < n_edges) atomicAdd(&g_cnt[__ldg(dst + i)], 1);  // fire-and-forget RED
}

// Phase 1: coalesced reduction of each 1024-int chunk (256 thr x int4)
__global__ __launch_bounds__(256) void scan1_kernel(int n) {
    __shared__ int red[256];
    int b = blockIdx.x, t = threadIdx.x;
    int i = b * 1024 + t * 4;
    int s = 0;
    if (i + 3 < n) {
        int4 v = *(const int4*)(g_cnt + i);
        s = (v.x + v.y) + (v.z + v.w);
    } else {
        for (int j = 0; j < 4; j++) if (i + j < n) s += g_cnt[i + j];
    }
    red[t] = s;
    __syncthreads();
    for (int off = 128; off > 0; off >>= 1) {
        if (t < off) red[t] += red[t + off];
        __syncthreads();
    }
    if (t == 0) g_bsum[b] = red[0];
}

// Phase 2: single 128-thread block scans the (<=128) chunk sums
__global__ __launch_bounds__(128) void scan2_kernel(int nchunk, int n_edges, int n) {
    __shared__ int ws[4];
    int t = threadIdx.x;
    int v = (t < nchunk) ? g_bsum[t] : 0;
    int lane = t & 31, wid = t >> 5;
    int p = v;
#pragma unroll
    for (int o = 1; o < 32; o <<= 1) {
        int x = __shfl_up_sync(0xffffffffu, p, o);
        if (lane >= o) p += x;
    }
    if (lane == 31) ws[wid] = p;
    __syncthreads();
    if (t == 0) {
        int r = 0;
        for (int w = 0; w < 4; w++) { int x = ws[w]; ws[w] = r; r += x; }
    }
    __syncthreads();
    if (t < nchunk) g_bbase[t] = (p - v) + ws[wid];
    if (t == 0) g_rs[n] = n_edges;  // total = every edge counted
}

// Phase 3: block-local exclusive scan of each 1024-chunk + base -> rs, cur
__global__ __launch_bounds__(256) void scan3_kernel(int n) {
    __shared__ int ws[8];
    int b = blockIdx.x, t = threadIdx.x;
    int i = b * 1024 + t * 4;
    int4 v = make_int4(0, 0, 0, 0);
    bool full = (i + 3 < n);
    if (full) v = *(const int4*)(g_cnt + i);
    else {
        int tmp[4] = {0, 0, 0, 0};
        for (int j = 0; j < 4; j++) if (i + j < n) tmp[j] = g_cnt[i + j];
        v = make_int4(tmp[0], tmp[1], tmp[2], tmp[3]);
    }
    int tsum = (v.x + v.y) + (v.z + v.w);
    int lane = t & 31, wid = t >> 5;
    int p = tsum;
#pragma unroll
    for (int o = 1; o < 32; o <<= 1) {
        int x = __shfl_up_sync(0xffffffffu, p, o);
        if (lane >= o) p += x;
    }
    if (lane == 31) ws[wid] = p;
    __syncthreads();
    if (t == 0) {
        int r = 0;
        for (int w = 0; w < 8; w++) { int x = ws[w]; ws[w] = r; r += x; }
    }
    __syncthreads();
    int ex = (p - tsum) + ws[wid] + g_bbase[b];
    int4 pre;
    pre.x = ex;
    pre.y = ex + v.x;
    pre.z = pre.y + v.y;
    pre.w = pre.z + v.z;
    if (full) {
        *(int4*)(g_rs + i) = pre;
        *(int4*)(g_cur + i) = pre;
    } else {
        int pr[4] = {pre.x, pre.y, pre.z, pre.w};
        for (int j = 0; j < 4; j++)
            if (i + j < n) { g_rs[i + j] = pr[j]; g_cur[i + j] = pr[j]; }
    }
}

// Placement: 4 independent edges/thread -> 4 concurrent ATOMG round-trips
__global__ void place_kernel(const int* __restrict__ src,
                             const int* __restrict__ dst, int n_edges) {
    int base = (blockIdx.x * blockDim.x + threadIdx.x) * 4;
#pragma unroll
    for (int j = 0; j < 4; j++) {
        int e = base + j;
        if (e < n_edges) {
            int p = atomicAdd(&g_cur[__ldg(dst + e)], 1);
            g_esrc[p] = __ldg(src + e);
        }
    }
}

// ---------------------------------------------------------------------------
// Tiled GEMM: Y[row] = act(X[row]) @ W, K=64 fixed, N in {64,32}.
// Block = 128 threads, 128-row tile; thread = 8 rows x (N/8) cols.
// A staged in smem XOR-swizzled; inner product uses packed fma.rn.f32x2.
// ---------------------------------------------------------------------------
#define FMA2(acc_, a_, b_) \
    asm("fma.rn.f32x2 %0, %1, %2, %0;" : "+l"(acc_) : "l"(a_), "l"(b_))

template <int N, bool ACT>
__global__ __launch_bounds__(128) void transform_kernel(
    const float* __restrict__ X, const float* __restrict__ W,
    const float* __restrict__ bin, float* __restrict__ Y, int n) {
    __shared__ float As[128 * 64];
    __shared__ float Ws[64 * N + (ACT ? 64 : 0)];
    float* bs = Ws + 64 * N;

    int tid = threadIdx.x;
    for (int i = tid; i < 64 * N; i += 128) Ws[i] = W[i];
    if (ACT && tid < 64) bs[tid] = bin[tid];
    __syncthreads();

    int blk = blockIdx.x * 128;
#pragma unroll
    for (int i = 0; i < 16; i++) {
        int idx = i * 128 + tid;
        int row = idx >> 4, c = idx & 15;
        int gr = blk + row;
        float4 v = make_float4(0.f, 0.f, 0.f, 0.f);
        if (gr < n) v = *(const float4*)(X + (size_t)gr * 64 + c * 4);
        float vv[4] = {v.x, v.y, v.z, v.w};
        int rm = row & 31;
#pragma unroll
        for (int j = 0; j < 4; j++) {
            float x = vv[j];
            if (ACT) x = fmaxf(x + bs[c * 4 + j], 0.f);
            As[row * 64 + ((c * 4 + j) ^ rm)] = x;
        }
    }
    __syncthreads();

    const int CT = N / 8;
    const int CP = CT / 2;
    int tr = tid >> 3, tc = tid & 7;

    unsigned long long acc[8][CP];
#pragma unroll
    for (int r = 0; r < 8; r++)
#pragma unroll
        for (int p = 0; p < CP; p++) acc[r][p] = 0ULL;

    int rowoff[8], rmask[8];
#pragma unroll
    for (int r = 0; r < 8; r++) {
        int row = tr * 8 + r;
        rowoff[r] = row * 64;
        rmask[r] = row & 31;
    }

#pragma unroll 4
    for (int k = 0; k < 64; k++) {
        unsigned long long b[CP];
#pragma unroll
        for (int p = 0; p < CP; p++)
            b[p] = *(const unsigned long long*)(Ws + k * N + tc * CT + 2 * p);
#pragma unroll
        for (int r = 0; r < 8; r++) {
            float a = As[rowoff[r] + (k ^ rmask[r])];
            unsigned int au = __float_as_uint(a);
            unsigned long long a2;
            asm("mov.b64 %0, {%1, %1};" : "=l"(a2) : "r"(au));
#pragma unroll
            for (int p = 0; p < CP; p++) FMA2(acc[r][p], a2, b[p]);
        }
    }

#pragma unroll
    for (int r = 0; r < 8; r++) {
        int gr = blk + tr * 8 + r;
        if (gr >= n) continue;
        float* yr = Y + (size_t)gr * N + tc * CT;
#pragma unroll
        for (int p = 0; p < CP; p += 2) {
            unsigned int l0, h0, l1, h1;
            asm("mov.b64 {%0, %1}, %2;" : "=r"(l0), "=r"(h0) : "l"(acc[r][p]));
            asm("mov.b64 {%0, %1}, %2;" : "=r"(l1), "=r"(h1) : "l"(acc[r][p + 1]));
            float4 o = make_float4(__uint_as_float(l0), __uint_as_float(h0),
                                   __uint_as_float(l1), __uint_as_float(h1));
            *(float4*)(yr + 2 * p) = o;
        }
    }
}

// ---------------------------------------------------------------------------
// CSR gather-sum, 64-wide rows: 16 lanes x float4 per node.
// ---------------------------------------------------------------------------
__global__ void gather64_kernel(const float* __restrict__ F,
                                float* __restrict__ O, int n) {
    int g = blockIdx.x * blockDim.x + threadIdx.x;
    int node = g >> 4, lane = g & 15;
    if (node >= n) return;
    int s = g_rs[node], e = g_rs[node + 1];
    float4 acc = make_float4(0.f, 0.f, 0.f, 0.f);
    int i = s;
    for (; i + 4 <= e; i += 4) {
        int s0 = __ldg(g_esrc + i),     s1 = __ldg(g_esrc + i + 1);
        int s2 = __ldg(g_esrc + i + 2), s3 = __ldg(g_esrc + i + 3);
        float4 v0 = *(const float4*)(F + (size_t)s0 * 64 + lane * 4);
        float4 v1 = *(const float4*)(F + (size_t)s1 * 64 + lane * 4);
        float4 v2 = *(const float4*)(F + (size_t)s2 * 64 + lane * 4);
        float4 v3 = *(const float4*)(F + (size_t)s3 * 64 + lane * 4);
        acc.x += (v0.x + v1.x) + (v2.x + v3.x);
        acc.y += (v0.y + v1.y) + (v2.y + v3.y);
        acc.z += (v0.z + v1.z) + (v2.z + v3.z);
        acc.w += (v0.w + v1.w) + (v2.w + v3.w);
    }
    for (; i < e; i++) {
        int si = __ldg(g_esrc + i);
        float4 v = *(const float4*)(F + (size_t)si * 64 + lane * 4);
        acc.x += v.x; acc.y += v.y; acc.z += v.z; acc.w += v.w;
    }
    *(float4*)(O + (size_t)node * 64 + lane * 4) = acc;
}

// ---------------------------------------------------------------------------
// CSR gather-sum, 32-wide rows, acc initialized with bias b2 (fused init).
// ---------------------------------------------------------------------------
__global__ void gather32_kernel(const float* __restrict__ F,
                                const float* __restrict__ b2,
                                float* __restrict__ O, int n) {
    int g = blockIdx.x * blockDim.x + threadIdx.x;
    int node = g >> 3, lane = g & 7;
    if (node >= n) return;
    int s = g_rs[node], e = g_rs[node + 1];
    float4 acc = *(const float4*)(b2 + lane * 4);
    int i = s;
    for (; i + 4 <= e; i += 4) {
        int s0 = __ldg(g_esrc + i),     s1 = __ldg(g_esrc + i + 1);
        int s2 = __ldg(g_esrc + i + 2), s3 = __ldg(g_esrc + i + 3);
        float4 v0 = *(const float4*)(F + (size_t)s0 * 32 + lane * 4);
        float4 v1 = *(const float4*)(F + (size_t)s1 * 32 + lane * 4);
        float4 v2 = *(const float4*)(F + (size_t)s2 * 32 + lane * 4);
        float4 v3 = *(const float4*)(F + (size_t)s3 * 32 + lane * 4);
        acc.x += (v0.x + v1.x) + (v2.x + v3.x);
        acc.y += (v0.y + v1.y) + (v2.y + v3.y);
        acc.z += (v0.z + v1.z) + (v2.z + v3.z);
        acc.w += (v0.w + v1.w) + (v2.w + v3.w);
    }
    for (; i < e; i++) {
        int si = __ldg(g_esrc + i);
        float4 v = *(const float4*)(F + (size_t)si * 32 + lane * 4);
        acc.x += v.x; acc.y += v.y; acc.z += v.z; acc.w += v.w;
    }
    *(float4*)(O + (size_t)node * 32 + lane * 4) = acc;
}

// ---------------------------------------------------------------------------
// kernel_launch
// ---------------------------------------------------------------------------
extern "C" void kernel_launch(void* const* d_in, const int* in_sizes, int n_in,
                              void* d_out, int out_size) {
    const float* features = (const float*)d_in[0];
    const int*   src      = (const int*)d_in[1];
    const int*   dst      = (const int*)d_in[2];
    const float* W1       = (const float*)d_in[3];
    const float* b1       = (const float*)d_in[4];
    const float* W2       = (const float*)d_in[5];
    const float* b2       = (const float*)d_in[6];
    float*       out      = (float*)d_out;

    int n_nodes = in_sizes[0] / 64;
    int n_edges = in_sizes[1];

    void *pf1, *pagg1, *pf2;
    cudaGetSymbolAddress(&pf1, g_f1);
    cudaGetSymbolAddress(&pagg1, g_agg1);
    cudaGetSymbolAddress(&pf2, g_f2);
    float* f1   = (float*)pf1;
    float* agg1 = (float*)pagg1;
    float* f2   = (float*)pf2;

    int nchunk = (n_nodes + 1023) / 1024;
    int tb = (n_nodes + 127) / 128;

    // CSR build
    {
        int n4 = (n_nodes + 3) / 4;
        zero_cnt_kernel<<<(n4 + 255) / 256, 256>>>(n4);
    }
    hist_kernel<<<(n_edges + 255) / 256, 256>>>(dst, n_edges);
    scan1_kernel<<<nchunk, 256>>>(n_nodes);
    scan2_kernel<<<1, 128>>>(nchunk, n_edges, n_nodes);
    scan3_kernel<<<nchunk, 256>>>(n_nodes);
    {
        int nthr = (n_edges + 3) / 4;
        place_kernel<<<(nthr + 255) / 256, 256>>>(src, dst, n_edges);
    }

    // Layer 1
    transform_kernel<64, false><<<tb, 128>>>(features, W1, nullptr, f1, n_nodes);
    gather64_kernel<<<(n_nodes * 16 + 255) / 256, 256>>>(f1, agg1, n_nodes);

    // Layer 2
    transform_kernel<32, true><<<tb, 128>>>(agg1, W2, b1, f2, n_nodes);
    gather32_kernel<<<(n_nodes * 8 + 255) / 256, 256>>>(f2, b2, out, n_nodes);
}

// round 4
// speedup vs baseline: 2.2207x; 1.0880x over previous
#include <cuda_runtime.h>
#include <cuda_fp16.h>
#include <cstddef>

#define NMAX 100000
#define EMAX 1600000
#define NCHUNK_MAX ((NMAX + 1023) / 1024 + 1)

// Scratch (__device__ globals; allocation-free rule)
__device__ __half g_f1h[NMAX * 64];   // features @ W1 (fp16 storage)
__device__ float  g_agg1[NMAX * 64];  // CSR gather of f1 (fp32)
__device__ __half g_f2h[NMAX * 32];   // relu(agg1 + b1) @ W2 (fp16 storage)
__device__ int    g_cnt[NMAX];        // in-degree histogram
__device__ int    g_rs[NMAX + 4];     // CSR row starts
__device__ int    g_cur[NMAX + 4];    // placement cursors
__device__ int    g_esrc[EMAX];       // CSR src lists grouped by dst
__device__ int    g_bsum[NCHUNK_MAX]; // per-1024-chunk sums

// ---------------------------------------------------------------------------
// CSR build
// ---------------------------------------------------------------------------
__global__ void zero_cnt_kernel(int n4) {
    int i = blockIdx.x * blockDim.x + threadIdx.x;
    if (i < n4) ((int4*)g_cnt)[i] = make_int4(0, 0, 0, 0);
}

// 4 edges/thread (int4 load) -> 4 concurrent REDs
__global__ void hist_kernel(const int* __restrict__ dst, int n_edges) {
    int base = (blockIdx.x * blockDim.x + threadIdx.x) * 4;
    if (base + 4 <= n_edges) {
        int4 d = *(const int4*)(dst + base);
        atomicAdd(&g_cnt[d.x], 1);
        atomicAdd(&g_cnt[d.y], 1);
        atomicAdd(&g_cnt[d.z], 1);
        atomicAdd(&g_cnt[d.w], 1);
    } else {
        for (int j = 0; j < 4; j++)
            if (base + j < n_edges) atomicAdd(&g_cnt[dst[base + j]], 1);
    }
}

// Phase 1: coalesced reduction of each 1024-int chunk (256 thr x int4)
__global__ __launch_bounds__(256) void scan1_kernel(int n) {
    __shared__ int red[256];
    int b = blockIdx.x, t = threadIdx.x;
    int i = b * 1024 + t * 4;
    int s = 0;
    if (i + 3 < n) {
        int4 v = *(const int4*)(g_cnt + i);
        s = (v.x + v.y) + (v.z + v.w);
    } else {
        for (int j = 0; j < 4; j++) if (i + j < n) s += g_cnt[i + j];
    }
    red[t] = s;
    __syncthreads();
    for (int off = 128; off > 0; off >>= 1) {
        if (t < off) red[t] += red[t + off];
        __syncthreads();
    }
    if (t == 0) g_bsum[b] = red[0];
}

// Phase 2 (merged): each block reduces chunk sums < b for its base, then does
// the block-local exclusive scan of its 1024-chunk and writes rs/cur (int4).
__global__ __launch_bounds__(256) void scan_rows_kernel(int n, int n_edges) {
    __shared__ int red[256];
    __shared__ int ws[8];
    int b = blockIdx.x, t = threadIdx.x;
    red[t] = (t < b) ? g_bsum[t] : 0;   // b < nchunk <= 256
    __syncthreads();
    for (int off = 128; off > 0; off >>= 1) {
        if (t < off) red[t] += red[t + off];
        __syncthreads();
    }
    int base = red[0];

    int i = b * 1024 + t * 4;
    int4 v = make_int4(0, 0, 0, 0);
    bool full = (i + 3 < n);
    if (full) v = *(const int4*)(g_cnt + i);
    else {
        int tmp[4] = {0, 0, 0, 0};
        for (int j = 0; j < 4; j++) if (i + j < n) tmp[j] = g_cnt[i + j];
        v = make_int4(tmp[0], tmp[1], tmp[2], tmp[3]);
    }
    int tsum = (v.x + v.y) + (v.z + v.w);
    int lane = t & 31, wid = t >> 5;
    int p = tsum;
#pragma unroll
    for (int o = 1; o < 32; o <<= 1) {
        int x = __shfl_up_sync(0xffffffffu, p, o);
        if (lane >= o) p += x;
    }
    if (lane == 31) ws[wid] = p;
    __syncthreads();
    if (t == 0) {
        int r = 0;
        for (int w = 0; w < 8; w++) { int x = ws[w]; ws[w] = r; r += x; }
    }
    __syncthreads();
    int ex = (p - tsum) + ws[wid] + base;
    int4 pre;
    pre.x = ex;
    pre.y = ex + v.x;
    pre.z = pre.y + v.y;
    pre.w = pre.z + v.z;
    if (full) {
        *(int4*)(g_rs + i) = pre;
        *(int4*)(g_cur + i) = pre;
    } else {
        int pr[4] = {pre.x, pre.y, pre.z, pre.w};
        for (int j = 0; j < 4; j++)
            if (i + j < n) { g_rs[i + j] = pr[j]; g_cur[i + j] = pr[j]; }
    }
    if (b == 0 && t == 0) g_rs[n] = n_edges;
}

// Placement: 8 independent edges/thread -> 8 concurrent ATOMG round-trips
__global__ void place_kernel(const int* __restrict__ src,
                             const int* __restrict__ dst, int n_edges) {
    int base = (blockIdx.x * blockDim.x + threadIdx.x) * 8;
    if (base + 8 <= n_edges) {
        int4 d0 = *(const int4*)(dst + base);
        int4 d1 = *(const int4*)(dst + base + 4);
        int4 s0 = *(const int4*)(src + base);
        int4 s1 = *(const int4*)(src + base + 4);
        int dd[8] = {d0.x, d0.y, d0.z, d0.w, d1.x, d1.y, d1.z, d1.w};
        int ss[8] = {s0.x, s0.y, s0.z, s0.w, s1.x, s1.y, s1.z, s1.w};
#pragma unroll
        for (int j = 0; j < 8; j++) {
            int p = atomicAdd(&g_cur[dd[j]], 1);
            g_esrc[p] = ss[j];
        }
    } else {
        for (int j = 0; j < 8; j++) {
            int e = base + j;
            if (e < n_edges) {
                int p = atomicAdd(&g_cur[dst[e]], 1);
                g_esrc[p] = src[e];
            }
        }
    }
}

// ---------------------------------------------------------------------------
// Tiled GEMM: Y[row] = act(X[row]) @ W, K=64, N in {64,32}; fp32 in, fp16 out.
// Block = 128 threads, 128-row tile; thread = 8 rows x (N/8) cols.
// A staged in smem XOR-swizzled; inner product uses packed fma.rn.f32x2.
// ---------------------------------------------------------------------------
#define FMA2(acc_, a_, b_) \
    asm("fma.rn.f32x2 %0, %1, %2, %0;" : "+l"(acc_) : "l"(a_), "l"(b_))

template <int N, bool ACT>
__global__ __launch_bounds__(128) void transform_kernel(
    const float* __restrict__ X, const float* __restrict__ W,
    const float* __restrict__ bin, __half* __restrict__ Y, int n) {
    __shared__ float As[128 * 64];
    __shared__ float Ws[64 * N + (ACT ? 64 : 0)];
    float* bs = Ws + 64 * N;

    int tid = threadIdx.x;
    for (int i = tid; i < 64 * N; i += 128) Ws[i] = W[i];
    if (ACT && tid < 64) bs[tid] = bin[tid];
    __syncthreads();

    int blk = blockIdx.x * 128;
#pragma unroll
    for (int i = 0; i < 16; i++) {
        int idx = i * 128 + tid;
        int row = idx >> 4, c = idx & 15;
        int gr = blk + row;
        float4 v = make_float4(0.f, 0.f, 0.f, 0.f);
        if (gr < n) v = *(const float4*)(X + (size_t)gr * 64 + c * 4);
        float vv[4] = {v.x, v.y, v.z, v.w};
        int rm = row & 31;
#pragma unroll
        for (int j = 0; j < 4; j++) {
            float x = vv[j];
            if (ACT) x = fmaxf(x + bs[c * 4 + j], 0.f);
            As[row * 64 + ((c * 4 + j) ^ rm)] = x;
        }
    }
    __syncthreads();

    const int CT = N / 8;
    const int CP = CT / 2;
    int tr = tid >> 3, tc = tid & 7;

    unsigned long long acc[8][CP];
#pragma unroll
    for (int r = 0; r < 8; r++)
#pragma unroll
        for (int p = 0; p < CP; p++) acc[r][p] = 0ULL;

    int rowoff[8], rmask[8];
#pragma unroll
    for (int r = 0; r < 8; r++) {
        int row = tr * 8 + r;
        rowoff[r] = row * 64;
        rmask[r] = row & 31;
    }

#pragma unroll 4
    for (int k = 0; k < 64; k++) {
        unsigned long long b[CP];
#pragma unroll
        for (int p = 0; p < CP; p++)
            b[p] = *(const unsigned long long*)(Ws + k * N + tc * CT + 2 * p);
#pragma unroll
        for (int r = 0; r < 8; r++) {
            float a = As[rowoff[r] + (k ^ rmask[r])];
            unsigned int au = __float_as_uint(a);
            unsigned long long a2;
            asm("mov.b64 %0, {%1, %1};" : "=l"(a2) : "r"(au));
#pragma unroll
            for (int p = 0; p < CP; p++) FMA2(acc[r][p], a2, b[p]);
        }
    }

#pragma unroll
    for (int r = 0; r < 8; r++) {
        int gr = blk + tr * 8 + r;
        if (gr >= n) continue;
        __half* yr = Y + (size_t)gr * N + tc * CT;
        unsigned int h[CP];
#pragma unroll
        for (int p = 0; p < CP; p++) {
            unsigned int lo, hi;
            asm("mov.b64 {%0, %1}, %2;" : "=r"(lo), "=r"(hi) : "l"(acc[r][p]));
            __half2 hp = __floats2half2_rn(__uint_as_float(lo), __uint_as_float(hi));
            h[p] = *(unsigned int*)&hp;
        }
        if (CP == 4) {
            *(int4*)yr = make_int4((int)h[0], (int)h[1], (int)h[2], (int)h[3]);
        } else {  // CP == 2
            *(int2*)yr = make_int2((int)h[0], (int)h[1]);
        }
    }
}

// Accumulate 8 halves (int4) into 8 fp32 accumulators
__device__ __forceinline__ void acc8h(float* acc, int4 v) {
    __half2 h0 = *(__half2*)&v.x, h1 = *(__half2*)&v.y;
    __half2 h2 = *(__half2*)&v.z, h3 = *(__half2*)&v.w;
    float2 f0 = __half22float2(h0), f1 = __half22float2(h1);
    float2 f2 = __half22float2(h2), f3 = __half22float2(h3);
    acc[0] += f0.x; acc[1] += f0.y; acc[2] += f1.x; acc[3] += f1.y;
    acc[4] += f2.x; acc[5] += f2.y; acc[6] += f3.x; acc[7] += f3.y;
}

// ---------------------------------------------------------------------------
// CSR gather-sum, 64-wide fp16 rows -> fp32 out: 8 lanes x 8 halves per node.
// ---------------------------------------------------------------------------
__global__ void gather64h_kernel(const __half* __restrict__ F,
                                 float* __restrict__ O, int n) {
    int g = blockIdx.x * blockDim.x + threadIdx.x;
    int node = g >> 3, lane = g & 7;
    if (node >= n) return;
    int s = g_rs[node], e = g_rs[node + 1];
    float acc[8];
#pragma unroll
    for (int j = 0; j < 8; j++) acc[j] = 0.f;
    int i = s;
    for (; i + 4 <= e; i += 4) {
        int s0 = __ldg(g_esrc + i),     s1 = __ldg(g_esrc + i + 1);
        int s2 = __ldg(g_esrc + i + 2), s3 = __ldg(g_esrc + i + 3);
        int4 v0 = *(const int4*)(F + (size_t)s0 * 64 + lane * 8);
        int4 v1 = *(const int4*)(F + (size_t)s1 * 64 + lane * 8);
        int4 v2 = *(const int4*)(F + (size_t)s2 * 64 + lane * 8);
        int4 v3 = *(const int4*)(F + (size_t)s3 * 64 + lane * 8);
        acc8h(acc, v0); acc8h(acc, v1); acc8h(acc, v2); acc8h(acc, v3);
    }
    for (; i < e; i++) {
        int si = __ldg(g_esrc + i);
        int4 v = *(const int4*)(F + (size_t)si * 64 + lane * 8);
        acc8h(acc, v);
    }
    float* op = O + (size_t)node * 64 + lane * 8;
    *(float4*)op       = make_float4(acc[0], acc[1], acc[2], acc[3]);
    *(float4*)(op + 4) = make_float4(acc[4], acc[5], acc[6], acc[7]);
}

// ---------------------------------------------------------------------------
// CSR gather-sum, 32-wide fp16 rows, b2-initialized fp32 out:
// 4 lanes x 8 halves per node.
// ---------------------------------------------------------------------------
__global__ void gather32h_kernel(const __half* __restrict__ F,
                                 const float* __restrict__ b2,
                                 float* __restrict__ O, int n) {
    int g = blockIdx.x * blockDim.x + threadIdx.x;
    int node = g >> 2, lane = g & 3;
    if (node >= n) return;
    int s = g_rs[node], e = g_rs[node + 1];
    float acc[8];
    {
        float4 blo = *(const float4*)(b2 + lane * 8);
        float4 bhi = *(const float4*)(b2 + lane * 8 + 4);
        acc[0] = blo.x; acc[1] = blo.y; acc[2] = blo.z; acc[3] = blo.w;
        acc[4] = bhi.x; acc[5] = bhi.y; acc[6] = bhi.z; acc[7] = bhi.w;
    }
    int i = s;
    for (; i + 4 <= e; i += 4) {
        int s0 = __ldg(g_esrc + i),     s1 = __ldg(g_esrc + i + 1);
        int s2 = __ldg(g_esrc + i + 2), s3 = __ldg(g_esrc + i + 3);
        int4 v0 = *(const int4*)(F + (size_t)s0 * 32 + lane * 8);
        int4 v1 = *(const int4*)(F + (size_t)s1 * 32 + lane * 8);
        int4 v2 = *(const int4*)(F + (size_t)s2 * 32 + lane * 8);
        int4 v3 = *(const int4*)(F + (size_t)s3 * 32 + lane * 8);
        acc8h(acc, v0); acc8h(acc, v1); acc8h(acc, v2); acc8h(acc, v3);
    }
    for (; i < e; i++) {
        int si = __ldg(g_esrc + i);
        int4 v = *(const int4*)(F + (size_t)si * 32 + lane * 8);
        acc8h(acc, v);
    }
    float* op = O + (size_t)node * 32 + lane * 8;
    *(float4*)op       = make_float4(acc[0], acc[1], acc[2], acc[3]);
    *(float4*)(op + 4) = make_float4(acc[4], acc[5], acc[6], acc[7]);
}

// ---------------------------------------------------------------------------
// kernel_launch
// ---------------------------------------------------------------------------
extern "C" void kernel_launch(void* const* d_in, const int* in_sizes, int n_in,
                              void* d_out, int out_size) {
    const float* features = (const float*)d_in[0];
    const int*   src      = (const int*)d_in[1];
    const int*   dst      = (const int*)d_in[2];
    const float* W1       = (const float*)d_in[3];
    const float* b1       = (const float*)d_in[4];
    const float* W2       = (const float*)d_in[5];
    const float* b2       = (const float*)d_in[6];
    float*       out      = (float*)d_out;

    int n_nodes = in_sizes[0] / 64;
    int n_edges = in_sizes[1];

    void *pf1, *pagg1, *pf2;
    cudaGetSymbolAddress(&pf1, g_f1h);
    cudaGetSymbolAddress(&pagg1, g_agg1);
    cudaGetSymbolAddress(&pf2, g_f2h);
    __half* f1h  = (__half*)pf1;
    float*  agg1 = (float*)pagg1;
    __half* f2h  = (__half*)pf2;

    int nchunk = (n_nodes + 1023) / 1024;
    int tb = (n_nodes + 127) / 128;

    // CSR build
    {
        int n4 = (n_nodes + 3) / 4;
        zero_cnt_kernel<<<(n4 + 255) / 256, 256>>>(n4);
    }
    {
        int nthr = (n_edges + 3) / 4;
        hist_kernel<<<(nthr + 255) / 256, 256>>>(dst, n_edges);
    }
    scan1_kernel<<<nchunk, 256>>>(n_nodes);
    scan_rows_kernel<<<nchunk, 256>>>(n_nodes, n_edges);
    {
        int nthr = (n_edges + 7) / 8;
        place_kernel<<<(nthr + 255) / 256, 256>>>(src, dst, n_edges);
    }

    // Layer 1: f1h = X @ W1 (fp16) ; agg1 = segment_sum(f1h[src] -> dst) (fp32)
    transform_kernel<64, false><<<tb, 128>>>(features, W1, nullptr, f1h, n_nodes);
    gather64h_kernel<<<(n_nodes * 8 + 255) / 256, 256>>>(f1h, agg1, n_nodes);

    // Layer 2: f2h = relu(agg1 + b1) @ W2 (fp16) ; out = b2 + segment_sum(f2h)
    transform_kernel<32, true><<<tb, 128>>>(agg1, W2, b1, f2h, n_nodes);
    gather32h_kernel<<<(n_nodes * 4 + 255) / 256, 256>>>(f2h, b2, out, n_nodes);
}

// round 5
// speedup vs baseline: 2.2871x; 1.0299x over previous
#include <cuda_runtime.h>
#include <cuda_fp16.h>
#include <cstddef>

#define NMAX 100000
#define EMAX 1600000
#define NCHUNK_MAX ((NMAX + 1023) / 1024 + 1)

// Scratch (__device__ globals; allocation-free rule)
__device__ __half g_f1h[NMAX * 64];   // features @ W1 (fp16 storage)
__device__ __half g_f2h[NMAX * 32];   // relu(agg1 + b1) @ W2 (fp16 storage)
__device__ int    g_cnt[NMAX];        // in-degree histogram
__device__ int    g_rs[NMAX + 4];     // CSR row starts
__device__ int    g_cur[NMAX + 4];    // placement cursors
__device__ int    g_esrc[EMAX];       // CSR src lists grouped by dst
__device__ int    g_bsum[NCHUNK_MAX]; // per-1024-chunk sums

// ---------------------------------------------------------------------------
// CSR build
// ---------------------------------------------------------------------------
__global__ void zero_cnt_kernel(int n4) {
    int i = blockIdx.x * blockDim.x + threadIdx.x;
    if (i < n4) ((int4*)g_cnt)[i] = make_int4(0, 0, 0, 0);
}

__global__ void hist_kernel(const int* __restrict__ dst, int n_edges) {
    int base = (blockIdx.x * blockDim.x + threadIdx.x) * 4;
    if (base + 4 <= n_edges) {
        int4 d = *(const int4*)(dst + base);
        atomicAdd(&g_cnt[d.x], 1);
        atomicAdd(&g_cnt[d.y], 1);
        atomicAdd(&g_cnt[d.z], 1);
        atomicAdd(&g_cnt[d.w], 1);
    } else {
        for (int j = 0; j < 4; j++)
            if (base + j < n_edges) atomicAdd(&g_cnt[dst[base + j]], 1);
    }
}

// Phase 1: coalesced reduction of each 1024-int chunk (256 thr x int4)
__global__ __launch_bounds__(256) void scan1_kernel(int n) {
    __shared__ int red[256];
    int b = blockIdx.x, t = threadIdx.x;
    int i = b * 1024 + t * 4;
    int s = 0;
    if (i + 3 < n) {
        int4 v = *(const int4*)(g_cnt + i);
        s = (v.x + v.y) + (v.z + v.w);
    } else {
        for (int j = 0; j < 4; j++) if (i + j < n) s += g_cnt[i + j];
    }
    red[t] = s;
    __syncthreads();
    for (int off = 128; off > 0; off >>= 1) {
        if (t < off) red[t] += red[t + off];
        __syncthreads();
    }
    if (t == 0) g_bsum[b] = red[0];
}

// Phase 2: per-block reduce of chunk sums < b, then block-local scan -> rs/cur
__global__ __launch_bounds__(256) void scan_rows_kernel(int n, int n_edges) {
    __shared__ int red[256];
    __shared__ int ws[8];
    int b = blockIdx.x, t = threadIdx.x;
    red[t] = (t < b) ? g_bsum[t] : 0;
    __syncthreads();
    for (int off = 128; off > 0; off >>= 1) {
        if (t < off) red[t] += red[t + off];
        __syncthreads();
    }
    int base = red[0];

    int i = b * 1024 + t * 4;
    int4 v = make_int4(0, 0, 0, 0);
    bool full = (i + 3 < n);
    if (full) v = *(const int4*)(g_cnt + i);
    else {
        int tmp[4] = {0, 0, 0, 0};
        for (int j = 0; j < 4; j++) if (i + j < n) tmp[j] = g_cnt[i + j];
        v = make_int4(tmp[0], tmp[1], tmp[2], tmp[3]);
    }
    int tsum = (v.x + v.y) + (v.z + v.w);
    int lane = t & 31, wid = t >> 5;
    int p = tsum;
#pragma unroll
    for (int o = 1; o < 32; o <<= 1) {
        int x = __shfl_up_sync(0xffffffffu, p, o);
        if (lane >= o) p += x;
    }
    if (lane == 31) ws[wid] = p;
    __syncthreads();
    if (t == 0) {
        int r = 0;
        for (int w = 0; w < 8; w++) { int x = ws[w]; ws[w] = r; r += x; }
    }
    __syncthreads();
    int ex = (p - tsum) + ws[wid] + base;
    int4 pre;
    pre.x = ex;
    pre.y = ex + v.x;
    pre.z = pre.y + v.y;
    pre.w = pre.z + v.z;
    if (full) {
        *(int4*)(g_rs + i) = pre;
        *(int4*)(g_cur + i) = pre;
    } else {
        int pr[4] = {pre.x, pre.y, pre.z, pre.w};
        for (int j = 0; j < 4; j++)
            if (i + j < n) { g_rs[i + j] = pr[j]; g_cur[i + j] = pr[j]; }
    }
    if (b == 0 && t == 0) g_rs[n] = n_edges;
}

// Placement: 8 independent edges/thread -> 8 concurrent ATOMG round-trips
__global__ void place_kernel(const int* __restrict__ src,
                             const int* __restrict__ dst, int n_edges) {
    int base = (blockIdx.x * blockDim.x + threadIdx.x) * 8;
    if (base + 8 <= n_edges) {
        int4 d0 = *(const int4*)(dst + base);
        int4 d1 = *(const int4*)(dst + base + 4);
        int4 s0 = *(const int4*)(src + base);
        int4 s1 = *(const int4*)(src + base + 4);
        int dd[8] = {d0.x, d0.y, d0.z, d0.w, d1.x, d1.y, d1.z, d1.w};
        int ss[8] = {s0.x, s0.y, s0.z, s0.w, s1.x, s1.y, s1.z, s1.w};
#pragma unroll
        for (int j = 0; j < 8; j++) {
            int p = atomicAdd(&g_cur[dd[j]], 1);
            g_esrc[p] = ss[j];
        }
    } else {
        for (int j = 0; j < 8; j++) {
            int e = base + j;
            if (e < n_edges) {
                int p = atomicAdd(&g_cur[dst[e]], 1);
                g_esrc[p] = src[e];
            }
        }
    }
}

// ---------------------------------------------------------------------------
// Transform 1: f1h[row] = (X[row] @ W1) in fp16. Block=128 thr, 128-row tile,
// thread = 8 rows x 8 cols; smem XOR-swizzled A; packed fma.rn.f32x2.
// ---------------------------------------------------------------------------
#define FMA2(acc_, a_, b_) \
    asm("fma.rn.f32x2 %0, %1, %2, %0;" : "+l"(acc_) : "l"(a_), "l"(b_))

__global__ __launch_bounds__(128) void transform1_kernel(
    const float* __restrict__ X, const float* __restrict__ W,
    __half* __restrict__ Y, int n) {
    const int N = 64;
    __shared__ float As[128 * 64];
    __shared__ float Ws[64 * N];

    int tid = threadIdx.x;
    for (int i = tid; i < 64 * N; i += 128) Ws[i] = W[i];
    __syncthreads();

    int blk = blockIdx.x * 128;
#pragma unroll
    for (int i = 0; i < 16; i++) {
        int idx = i * 128 + tid;
        int row = idx >> 4, c = idx & 15;
        int gr = blk + row;
        float4 v = make_float4(0.f, 0.f, 0.f, 0.f);
        if (gr < n) v = *(const float4*)(X + (size_t)gr * 64 + c * 4);
        float vv[4] = {v.x, v.y, v.z, v.w};
        int rm = row & 31;
#pragma unroll
        for (int j = 0; j < 4; j++)
            As[row * 64 + ((c * 4 + j) ^ rm)] = vv[j];
    }
    __syncthreads();

    int tr = tid >> 3, tc = tid & 7;
    unsigned long long acc[8][4];
#pragma unroll
    for (int r = 0; r < 8; r++)
#pragma unroll
        for (int p = 0; p < 4; p++) acc[r][p] = 0ULL;

    int rowoff[8], rmask[8];
#pragma unroll
    for (int r = 0; r < 8; r++) {
        int row = tr * 8 + r;
        rowoff[r] = row * 64;
        rmask[r] = row & 31;
    }

#pragma unroll 4
    for (int k = 0; k < 64; k++) {
        unsigned long long b[4];
#pragma unroll
        for (int p = 0; p < 4; p++)
            b[p] = *(const unsigned long long*)(Ws + k * N + tc * 8 + 2 * p);
#pragma unroll
        for (int r = 0; r < 8; r++) {
            float a = As[rowoff[r] + (k ^ rmask[r])];
            unsigned int au = __float_as_uint(a);
            unsigned long long a2;
            asm("mov.b64 %0, {%1, %1};" : "=l"(a2) : "r"(au));
#pragma unroll
            for (int p = 0; p < 4; p++) FMA2(acc[r][p], a2, b[p]);
        }
    }

#pragma unroll
    for (int r = 0; r < 8; r++) {
        int gr = blk + tr * 8 + r;
        if (gr >= n) continue;
        __half* yr = Y + (size_t)gr * N + tc * 8;
        unsigned int h[4];
#pragma unroll
        for (int p = 0; p < 4; p++) {
            unsigned int lo, hi;
            asm("mov.b64 {%0, %1}, %2;" : "=r"(lo), "=r"(hi) : "l"(acc[r][p]));
            __half2 hp = __floats2half2_rn(__uint_as_float(lo), __uint_as_float(hi));
            h[p] = *(unsigned int*)&hp;
        }
        *(int4*)yr = make_int4((int)h[0], (int)h[1], (int)h[2], (int)h[3]);
    }
}

// Accumulate 8 halves (int4) into 8 fp32 accumulators
__device__ __forceinline__ void acc8h(float* acc, int4 v) {
    __half2 h0 = *(__half2*)&v.x, h1 = *(__half2*)&v.y;
    __half2 h2 = *(__half2*)&v.z, h3 = *(__half2*)&v.w;
    float2 f0 = __half22float2(h0), f1 = __half22float2(h1);
    float2 f2 = __half22float2(h2), f3 = __half22float2(h3);
    acc[0] += f0.x; acc[1] += f0.y; acc[2] += f1.x; acc[3] += f1.y;
    acc[4] += f2.x; acc[5] += f2.y; acc[6] += f3.x; acc[7] += f3.y;
}

// ---------------------------------------------------------------------------
// Fused layer 2: per node, gather 64 fp16 features (CSR sum, fp32 acc),
// apply relu(x + b1), multiply by W2 (64x32), store fp16 row of 32.
// Block = 256 threads = 32 nodes x 8 lanes. Node smem rows padded to 68
// floats so the 4 node-groups of a warp hit distinct banks in phase 2.
// ---------------------------------------------------------------------------
#define NSTRIDE 68
__global__ __launch_bounds__(256) void fused_layer2_kernel(
    const __half* __restrict__ F, const float* __restrict__ W2,
    const float* __restrict__ b1, __half* __restrict__ Y, int n) {
    __shared__ float Ns[32 * NSTRIDE];   // 32 node rows of 64 (padded)
    __shared__ float Ws[64 * 32];        // W2
    __shared__ float bs[64];             // b1

    int tid = threadIdx.x;
    for (int i = tid; i < 64 * 32; i += 256) Ws[i] = W2[i];
    if (tid < 64) bs[tid] = b1[tid];
    __syncthreads();

    int nl = tid >> 3;          // local node 0..31
    int lane = tid & 7;         // 8 lanes per node
    int node = blockIdx.x * 32 + nl;

    // Phase 1: gather this node's 64-feature sum (8 fp32 per lane)
    float acc[8];
#pragma unroll
    for (int j = 0; j < 8; j++) acc[j] = 0.f;

    if (node < n) {
        int s = g_rs[node], e = g_rs[node + 1];
        int i = s;
        for (; i + 4 <= e; i += 4) {
            int s0 = __ldg(g_esrc + i),     s1 = __ldg(g_esrc + i + 1);
            int s2 = __ldg(g_esrc + i + 2), s3 = __ldg(g_esrc + i + 3);
            int4 v0 = *(const int4*)(F + (size_t)s0 * 64 + lane * 8);
            int4 v1 = *(const int4*)(F + (size_t)s1 * 64 + lane * 8);
            int4 v2 = *(const int4*)(F + (size_t)s2 * 64 + lane * 8);
            int4 v3 = *(const int4*)(F + (size_t)s3 * 64 + lane * 8);
            acc8h(acc, v0); acc8h(acc, v1); acc8h(acc, v2); acc8h(acc, v3);
        }
        for (; i < e; i++) {
            int si = __ldg(g_esrc + i);
            int4 v = *(const int4*)(F + (size_t)si * 64 + lane * 8);
            acc8h(acc, v);
        }
    }
    // relu(x + b1) -> smem node row
    {
        float* row = Ns + nl * NSTRIDE + lane * 8;
#pragma unroll
        for (int j = 0; j < 8; j++)
            row[j] = fmaxf(acc[j] + bs[lane * 8 + j], 0.f);
    }
    __syncthreads();

    // Phase 2: y[node][lane*4 .. +3] = h[node] @ W2 columns
    unsigned long long oacc[2] = {0ULL, 0ULL};
    const float* hrow = Ns + nl * NSTRIDE;
#pragma unroll 8
    for (int k = 0; k < 64; k++) {
        float a = hrow[k];                       // broadcast within 8 lanes
        unsigned int au = __float_as_uint(a);
        unsigned long long a2;
        asm("mov.b64 %0, {%1, %1};" : "=l"(a2) : "r"(au));
        unsigned long long w0 = *(const unsigned long long*)(Ws + k * 32 + lane * 4);
        unsigned long long w1 = *(const unsigned long long*)(Ws + k * 32 + lane * 4 + 2);
        FMA2(oacc[0], a2, w0);
        FMA2(oacc[1], a2, w1);
    }
    if (node < n) {
        unsigned int l0, h0, l1, h1;
        asm("mov.b64 {%0, %1}, %2;" : "=r"(l0), "=r"(h0) : "l"(oacc[0]));
        asm("mov.b64 {%0, %1}, %2;" : "=r"(l1), "=r"(h1) : "l"(oacc[1]));
        __half2 p0 = __floats2half2_rn(__uint_as_float(l0), __uint_as_float(h0));
        __half2 p1 = __floats2half2_rn(__uint_as_float(l1), __uint_as_float(h1));
        __half* yr = Y + (size_t)node * 32 + lane * 4;
        *(int2*)yr = make_int2(*(int*)&p0, *(int*)&p1);
    }
}

// ---------------------------------------------------------------------------
// CSR gather-sum, 32-wide fp16 rows, b2-initialized fp32 out:
// 4 lanes x 8 halves per node.
// ---------------------------------------------------------------------------
__global__ void gather32h_kernel(const __half* __restrict__ F,
                                 const float* __restrict__ b2,
                                 float* __restrict__ O, int n) {
    int g = blockIdx.x * blockDim.x + threadIdx.x;
    int node = g >> 2, lane = g & 3;
    if (node >= n) return;
    int s = g_rs[node], e = g_rs[node + 1];
    float acc[8];
    {
        float4 blo = *(const float4*)(b2 + lane * 8);
        float4 bhi = *(const float4*)(b2 + lane * 8 + 4);
        acc[0] = blo.x; acc[1] = blo.y; acc[2] = blo.z; acc[3] = blo.w;
        acc[4] = bhi.x; acc[5] = bhi.y; acc[6] = bhi.z; acc[7] = bhi.w;
    }
    int i = s;
    for (; i + 4 <= e; i += 4) {
        int s0 = __ldg(g_esrc + i),     s1 = __ldg(g_esrc + i + 1);
        int s2 = __ldg(g_esrc + i + 2), s3 = __ldg(g_esrc + i + 3);
        int4 v0 = *(const int4*)(F + (size_t)s0 * 32 + lane * 8);
        int4 v1 = *(const int4*)(F + (size_t)s1 * 32 + lane * 8);
        int4 v2 = *(const int4*)(F + (size_t)s2 * 32 + lane * 8);
        int4 v3 = *(const int4*)(F + (size_t)s3 * 32 + lane * 8);
        acc8h(acc, v0); acc8h(acc, v1); acc8h(acc, v2); acc8h(acc, v3);
    }
    for (; i < e; i++) {
        int si = __ldg(g_esrc + i);
        int4 v = *(const int4*)(F + (size_t)si * 32 + lane * 8);
        acc8h(acc, v);
    }
    float* op = O + (size_t)node * 32 + lane * 8;
    *(float4*)op       = make_float4(acc[0], acc[1], acc[2], acc[3]);
    *(float4*)(op + 4) = make_float4(acc[4], acc[5], acc[6], acc[7]);
}

// ---------------------------------------------------------------------------
// kernel_launch
// ---------------------------------------------------------------------------
extern "C" void kernel_launch(void* const* d_in, const int* in_sizes, int n_in,
                              void* d_out, int out_size) {
    const float* features = (const float*)d_in[0];
    const int*   src      = (const int*)d_in[1];
    const int*   dst      = (const int*)d_in[2];
    const float* W1       = (const float*)d_in[3];
    const float* b1       = (const float*)d_in[4];
    const float* W2       = (const float*)d_in[5];
    const float* b2       = (const float*)d_in[6];
    float*       out      = (float*)d_out;

    int n_nodes = in_sizes[0] / 64;
    int n_edges = in_sizes[1];

    void *pf1, *pf2;
    cudaGetSymbolAddress(&pf1, g_f1h);
    cudaGetSymbolAddress(&pf2, g_f2h);
    __half* f1h = (__half*)pf1;
    __half* f2h = (__half*)pf2;

    int nchunk = (n_nodes + 1023) / 1024;
    int tb = (n_nodes + 127) / 128;

    // Transform1 first (longest independent work before gather)
    transform1_kernel<<<tb, 128>>>(features, W1, f1h, n_nodes);

    // CSR build
    {
        int n4 = (n_nodes + 3) / 4;
        zero_cnt_kernel<<<(n4 + 255) / 256, 256>>>(n4);
    }
    {
        int nthr = (n_edges + 3) / 4;
        hist_kernel<<<(nthr + 255) / 256, 256>>>(dst, n_edges);
    }
    scan1_kernel<<<nchunk, 256>>>(n_nodes);
    scan_rows_kernel<<<nchunk, 256>>>(n_nodes, n_edges);
    {
        int nthr = (n_edges + 7) / 8;
        place_kernel<<<(nthr + 255) / 256, 256>>>(src, dst, n_edges);
    }

    // Fused layer 2: gather f1h -> relu(+b1) -> @W2 -> f2h (fp16)
    {
        int blocks = (n_nodes + 31) / 32;
        fused_layer2_kernel<<<blocks, 256>>>(f1h, W2, b1, f2h, n_nodes);
    }

    // Output: out = b2 + segment_sum(f2h[src] -> dst)
    gather32h_kernel<<<(n_nodes * 4 + 255) / 256, 256>>>(f2h, b2, out, n_nodes);
}